// round 6
// baseline (speedup 1.0000x reference)
#include <cuda_runtime.h>

#define TPB      256
#define MAXGRID  16384   // 4194304 rows / 256

// Per-block partials: fully overwritten each launch (graph-deterministic).
__device__ float g_part[MAXGRID];
// Ticket counter: atom.inc with wrap (grid-1) returns to 0 after each
// complete launch, so graph replays are deterministic. Zero-init at load.
__device__ unsigned int g_count;

__device__ __forceinline__ float group_loss(float4 p, float4 q, float4 r) {
    float ax = p.y, ay = p.z, az = p.w;
    float bx = q.y, by = q.z, bz = q.w;
    float cx = r.y, cy = r.z, cz = r.w;

    float ia = rsqrtf(ax * ax + ay * ay + az * az);
    float ib = rsqrtf(bx * bx + by * by + bz * bz);
    float ic = rsqrtf(cx * cx + cy * cy + cz * cz);
    ax *= ia; ay *= ia; az *= ia;
    bx *= ib; by *= ib; bz *= ib;
    cx *= ic; cy *= ic; cz *= ic;

    float daa = ax * ax + ay * ay + az * az - 1.0f;
    float dbb = bx * bx + by * by + bz * bz - 1.0f;
    float dcc = cx * cx + cy * cy + cz * cz - 1.0f;
    float dab = ax * bx + ay * by + az * bz;
    float dac = ax * cx + ay * cy + az * cz;
    float dbc = bx * cx + by * cy + bz * cz;

    return daa * daa + dbb * dbb + dcc * dcc
         + 2.0f * (dab * dab + dac * dac + dbc * dbc);
}

__global__ void __launch_bounds__(TPB) loss_kernel(const float4* __restrict__ in,
                                                   int nrows, int grid,
                                                   float* __restrict__ out) {
    const int tid = threadIdx.x;
    const int row = blockIdx.x * TPB + tid;

    float acc = 0.0f;
    if (row < nrows) {
        const float4* __restrict__ r = in + (size_t)row * 6;
        // 6 front-batched LDG.128 — exact R1 hot-path shape.
        float4 r0 = r[0];
        float4 r1 = r[1];
        float4 r2 = r[2];
        float4 r3 = r[3];
        float4 r4 = r[4];
        float4 r5 = r[5];
        acc  = group_loss(r0, r1, r2);
        acc += group_loss(r3, r4, r5);
    }

    // Block reduction.
    #pragma unroll
    for (int off = 16; off > 0; off >>= 1)
        acc += __shfl_xor_sync(0xFFFFFFFFu, acc, off);

    __shared__ float ws[TPB / 32];
    __shared__ unsigned int s_ticket;
    const int lane = tid & 31;
    const int warp = tid >> 5;
    if (lane == 0) ws[warp] = acc;
    __syncthreads();

    if (warp == 0) {
        acc = (lane < TPB / 32) ? ws[lane] : 0.0f;
        #pragma unroll
        for (int off = 4; off > 0; off >>= 1)
            acc += __shfl_xor_sync(0xFFFFFFFFu, acc, off);
        if (lane == 0) {
            g_part[blockIdx.x] = acc;
            // Release-ordered ticket: orders the g_part store before the
            // counter bump at gpu scope WITHOUT a full membar/L1-flush.
            // acq_rel also gives the winning (last) block acquire semantics
            // for its subsequent g_part reads. Wraps to 0 at grid-1.
            unsigned int t;
            asm volatile("atom.acq_rel.gpu.global.inc.u32 %0, [%1], %2;"
                         : "=r"(t)
                         : "l"(&g_count), "r"((unsigned)grid - 1)
                         : "memory");
            s_ticket = t;
        }
    }
    __syncthreads();

    // Last-arriving block: reduce all partials (L2-hot; L1 is per-launch
    // flushed so no stale lines — read via L2 anyway).
    if (s_ticket == (unsigned)grid - 1) {
        double a = 0.0;
        for (int i = tid; i < grid; i += TPB)
            a += (double)__ldcg(&g_part[i]);

        #pragma unroll
        for (int off = 16; off > 0; off >>= 1)
            a += __shfl_xor_sync(0xFFFFFFFFu, a, off);

        __shared__ double ds[TPB / 32];
        if (lane == 0) ds[warp] = a;
        __syncthreads();

        if (warp == 0) {
            a = (lane < TPB / 32) ? ds[lane] : 0.0;
            #pragma unroll
            for (int off = 4; off > 0; off >>= 1)
                a += __shfl_xor_sync(0xFFFFFFFFu, a, off);
            if (lane == 0) out[0] = (float)(a / (double)nrows);
        }
    }
}

extern "C" void kernel_launch(void* const* d_in, const int* in_sizes, int n_in,
                              void* d_out, int out_size) {
    const float4* in = (const float4*)d_in[0];
    float* out = (float*)d_out;
    int nrows = in_sizes[0] / 24;  // 24 floats per row
    int grid = (nrows + TPB - 1) / TPB;
    if (grid > MAXGRID) grid = MAXGRID;  // shapes are fixed: 16384

    loss_kernel<<<grid, TPB>>>(in, nrows, grid, out);
}

// round 7
// speedup vs baseline: 1.1932x; 1.1932x over previous
#include <cuda_runtime.h>

#define TPB 256

// Global double accumulator. Zero at load; finalize_kernel resets it to 0
// after consuming it, so every launch (and every graph replay) starts from 0.
__device__ double g_accum;

__device__ __forceinline__ float group_loss(float4 p, float4 q, float4 r) {
    float ax = p.y, ay = p.z, az = p.w;
    float bx = q.y, by = q.z, bz = q.w;
    float cx = r.y, cy = r.z, cz = r.w;

    float ia = rsqrtf(ax * ax + ay * ay + az * az);
    float ib = rsqrtf(bx * bx + by * by + bz * bz);
    float ic = rsqrtf(cx * cx + cy * cy + cz * cz);
    ax *= ia; ay *= ia; az *= ia;
    bx *= ib; by *= ib; bz *= ib;
    cx *= ic; cy *= ic; cz *= ic;

    float daa = ax * ax + ay * ay + az * az - 1.0f;
    float dbb = bx * bx + by * by + bz * bz - 1.0f;
    float dcc = cx * cx + cy * cy + cz * cz - 1.0f;
    float dab = ax * bx + ay * by + az * bz;
    float dac = ax * cx + ay * cy + az * cz;
    float dbc = bx * cx + by * cy + bz * cz;

    return daa * daa + dbb * dbb + dcc * dcc
         + 2.0f * (dab * dab + dac * dac + dbc * dbc);
}

__global__ void __launch_bounds__(TPB) loss_kernel(const float4* __restrict__ in,
                                                   int nrows) {
    int idx = blockIdx.x * TPB + threadIdx.x;

    float loss = 0.0f;
    if (idx < nrows) {
        const float4* __restrict__ row = in + (size_t)idx * 6;
        float4 r0 = row[0];
        float4 r1 = row[1];
        float4 r2 = row[2];
        float4 r3 = row[3];
        float4 r4 = row[4];
        float4 r5 = row[5];
        loss  = group_loss(r0, r1, r2);
        loss += group_loss(r3, r4, r5);
    }

    // Warp reduction
    #pragma unroll
    for (int off = 16; off > 0; off >>= 1)
        loss += __shfl_xor_sync(0xFFFFFFFFu, loss, off);

    __shared__ float warp_sums[TPB / 32];
    int lane = threadIdx.x & 31;
    int warp = threadIdx.x >> 5;
    if (lane == 0) warp_sums[warp] = loss;
    __syncthreads();

    if (warp == 0) {
        loss = (lane < TPB / 32) ? warp_sums[lane] : 0.0f;
        #pragma unroll
        for (int off = 4; off > 0; off >>= 1)
            loss += __shfl_xor_sync(0xFFFFFFFFu, loss, off);
        if (lane == 0)
            atomicAdd(&g_accum, (double)loss);  // REDG: no-return, cheap
    }
}

__global__ void finalize_kernel(float* out, int nrows) {
    out[0] = (float)(g_accum / (double)nrows);
    g_accum = 0.0;  // reset for the next launch / graph replay
}

extern "C" void kernel_launch(void* const* d_in, const int* in_sizes, int n_in,
                              void* d_out, int out_size) {
    const float4* in = (const float4*)d_in[0];
    float* out = (float*)d_out;
    int nrows = in_sizes[0] / 24;  // 24 floats per row
    int blocks = (nrows + TPB - 1) / TPB;

    loss_kernel<<<blocks, TPB>>>(in, nrows);
    finalize_kernel<<<1, 1>>>(out, nrows);
}

// round 8
// speedup vs baseline: 1.3122x; 1.0997x over previous
#include <cuda_runtime.h>

#define TPB    256
#define WARPS  (TPB / 32)
#define PLANE  199                  // plane stride: > f(191)=196, odd
#define WSMEM  (3 * PLANE)          // 3 component planes per warp

// Global double accumulator. Zero at load; finalize_kernel resets it after
// consuming, so every launch / graph replay starts from 0.
__device__ double g_accum;

__global__ void __launch_bounds__(TPB) loss_kernel(const float4* __restrict__ in,
                                                   int nrows) {
    __shared__ float s[WARPS * WSMEM];

    const int tid  = threadIdx.x;
    const int lane = tid & 31;
    const int w    = tid >> 5;
    const int warp_row0 = blockIdx.x * TPB + w * 32;

    float acc = 0.0f;

    if (warp_row0 + 32 <= nrows) {
        // ---- 1) Coalesced load: 32 rows = 192 float4 = 3072 contiguous bytes ----
        const float4* __restrict__ g4 = in + (size_t)warp_row0 * 6;
        float4 v[6];
        #pragma unroll
        for (int i = 0; i < 6; i++)
            v[i] = g4[i * 32 + lane];

        // ---- 2) Normalize in registers: each float4 holds one 3-vector (y,z,w) ----
        float nx[6], ny[6], nz[6];
        #pragma unroll
        for (int i = 0; i < 6; i++) {
            float x = v[i].y, y = v[i].z, z = v[i].w;
            float inv = rsqrtf(x * x + y * y + z * z);
            nx[i] = x * inv; ny[i] = y * inv; nz[i] = z * inv;
        }

        // ---- 3) Plane-major smem store, skew f(k)=k+(k>>5) ----
        // k = 32*i + lane -> f(k) = 33*i + lane: lane-consecutive => conflict-free.
        float* sw = s + w * WSMEM;
        #pragma unroll
        for (int i = 0; i < 6; i++) {
            int fi = 33 * i + lane;
            sw[0 * PLANE + fi] = nx[i];
            sw[1 * PLANE + fi] = ny[i];
            sw[2 * PLANE + fi] = nz[i];
        }
        __syncwarp();

        // ---- 4) Gather own row (local row = lane): vectors m = 6*lane + j ----
        float ax[6], ay[6], az[6];
        #pragma unroll
        for (int j = 0; j < 6; j++) {
            int m  = 6 * lane + j;
            int fm = m + (m >> 5);
            ax[j] = sw[0 * PLANE + fm];
            ay[j] = sw[1 * PLANE + fm];
            az[j] = sw[2 * PLANE + fm];
        }

        // Off-diagonal Gram terms only: diag (|n|^2-1)^2 ~ 1e-13 relative, dropped.
        #pragma unroll
        for (int g = 0; g < 2; g++) {
            int b = 3 * g;
            float dab = ax[b]   * ax[b+1] + ay[b]   * ay[b+1] + az[b]   * az[b+1];
            float dac = ax[b]   * ax[b+2] + ay[b]   * ay[b+2] + az[b]   * az[b+2];
            float dbc = ax[b+1] * ax[b+2] + ay[b+1] * ay[b+2] + az[b+1] * az[b+2];
            acc += 2.0f * (dab * dab + dac * dac + dbc * dbc);
        }
    } else {
        // ---- Tail (partial warp): direct per-row loads ----
        int row = warp_row0 + lane;
        if (row < nrows) {
            const float4* __restrict__ rp = in + (size_t)row * 6;
            #pragma unroll
            for (int g = 0; g < 2; g++) {
                float4 p = rp[3*g], q = rp[3*g+1], r = rp[3*g+2];
                float ia = rsqrtf(p.y*p.y + p.z*p.z + p.w*p.w);
                float ib = rsqrtf(q.y*q.y + q.z*q.z + q.w*q.w);
                float ic = rsqrtf(r.y*r.y + r.z*r.z + r.w*r.w);
                float a0 = p.y*ia, a1 = p.z*ia, a2 = p.w*ia;
                float b0 = q.y*ib, b1 = q.z*ib, b2 = q.w*ib;
                float c0 = r.y*ic, c1 = r.z*ic, c2 = r.w*ic;
                float dab = a0*b0 + a1*b1 + a2*b2;
                float dac = a0*c0 + a1*c1 + a2*c2;
                float dbc = b0*c0 + b1*c1 + b2*c2;
                acc += 2.0f * (dab*dab + dac*dac + dbc*dbc);
            }
        }
    }

    // ---- Block reduction ----
    #pragma unroll
    for (int off = 16; off > 0; off >>= 1)
        acc += __shfl_xor_sync(0xFFFFFFFFu, acc, off);

    __shared__ float ws[WARPS];
    if (lane == 0) ws[w] = acc;
    __syncthreads();

    if (w == 0) {
        acc = (lane < WARPS) ? ws[lane] : 0.0f;
        #pragma unroll
        for (int off = 4; off > 0; off >>= 1)
            acc += __shfl_xor_sync(0xFFFFFFFFu, acc, off);
        if (lane == 0)
            atomicAdd(&g_accum, (double)acc);  // REDG, no-return
    }
}

__global__ void finalize_kernel(float* out, int nrows) {
    out[0] = (float)(g_accum / (double)nrows);
    g_accum = 0.0;  // reset for next launch / graph replay
}

extern "C" void kernel_launch(void* const* d_in, const int* in_sizes, int n_in,
                              void* d_out, int out_size) {
    const float4* in = (const float4*)d_in[0];
    float* out = (float*)d_out;
    int nrows = in_sizes[0] / 24;  // 24 floats per row
    int blocks = (nrows + TPB - 1) / TPB;

    loss_kernel<<<blocks, TPB>>>(in, nrows);
    finalize_kernel<<<1, 1>>>(out, nrows);
}

// round 9
// speedup vs baseline: 1.3953x; 1.0633x over previous
#include <cuda_runtime.h>

#define TPB    256
#define WARPS  (TPB / 32)
#define PLANE  199                  // plane stride: > f(191)=196, odd
#define WSMEM  (3 * PLANE)          // 3 component planes per warp

// Global double accumulator. Zero at load; finalize_kernel resets it after
// consuming, so every launch / graph replay starts from 0.
__device__ double g_accum;

__device__ __forceinline__ float4 ldcs_f4(const float4* p) {
    float4 v;
    asm volatile("ld.global.cs.v4.f32 {%0,%1,%2,%3}, [%4];"
                 : "=f"(v.x), "=f"(v.y), "=f"(v.z), "=f"(v.w)
                 : "l"(p));
    return v;
}

__global__ void __launch_bounds__(TPB) loss_kernel(const float4* __restrict__ in,
                                                   int nrows) {
    __shared__ float s[WARPS * WSMEM];

    const int tid  = threadIdx.x;
    const int lane = tid & 31;
    const int w    = tid >> 5;
    const int warp_row0 = blockIdx.x * TPB + w * 32;

    float acc = 0.0f;

    if (warp_row0 + 32 <= nrows) {
        // ---- 1) Coalesced streaming load: 32 rows = 3072 contiguous bytes ----
        // .cs = evict-first in L1+L2: data is touched exactly once, don't let
        // the 400MB stream thrash the 126MB L2 at normal insertion priority.
        const float4* __restrict__ g4 = in + (size_t)warp_row0 * 6;
        float4 v[6];
        #pragma unroll
        for (int i = 0; i < 6; i++)
            v[i] = ldcs_f4(g4 + i * 32 + lane);

        // ---- 2) Normalize in registers (each float4 = one 3-vector y,z,w) ----
        float nx[6], ny[6], nz[6];
        #pragma unroll
        for (int i = 0; i < 6; i++) {
            float x = v[i].y, y = v[i].z, z = v[i].w;
            float inv = rsqrtf(x * x + y * y + z * z);
            nx[i] = x * inv; ny[i] = y * inv; nz[i] = z * inv;
        }

        // ---- 3) Plane-major smem store, skew f(k)=k+(k>>5) ----
        float* sw = s + w * WSMEM;
        #pragma unroll
        for (int i = 0; i < 6; i++) {
            int fi = 33 * i + lane;
            sw[0 * PLANE + fi] = nx[i];
            sw[1 * PLANE + fi] = ny[i];
            sw[2 * PLANE + fi] = nz[i];
        }
        __syncwarp();

        // ---- 4) Gather own row (local row = lane) ----
        float ax[6], ay[6], az[6];
        #pragma unroll
        for (int j = 0; j < 6; j++) {
            int m  = 6 * lane + j;
            int fm = m + (m >> 5);
            ax[j] = sw[0 * PLANE + fm];
            ay[j] = sw[1 * PLANE + fm];
            az[j] = sw[2 * PLANE + fm];
        }

        // Off-diagonal Gram terms only (diag ~1e-13 relative, dropped).
        #pragma unroll
        for (int g = 0; g < 2; g++) {
            int b = 3 * g;
            float dab = ax[b]   * ax[b+1] + ay[b]   * ay[b+1] + az[b]   * az[b+1];
            float dac = ax[b]   * ax[b+2] + ay[b]   * ay[b+2] + az[b]   * az[b+2];
            float dbc = ax[b+1] * ax[b+2] + ay[b+1] * ay[b+2] + az[b+1] * az[b+2];
            acc += 2.0f * (dab * dab + dac * dac + dbc * dbc);
        }
    } else {
        // ---- Tail (partial warp): direct per-row loads ----
        int row = warp_row0 + lane;
        if (row < nrows) {
            const float4* __restrict__ rp = in + (size_t)row * 6;
            #pragma unroll
            for (int g = 0; g < 2; g++) {
                float4 p = rp[3*g], q = rp[3*g+1], r = rp[3*g+2];
                float ia = rsqrtf(p.y*p.y + p.z*p.z + p.w*p.w);
                float ib = rsqrtf(q.y*q.y + q.z*q.z + q.w*q.w);
                float ic = rsqrtf(r.y*r.y + r.z*r.z + r.w*r.w);
                float a0 = p.y*ia, a1 = p.z*ia, a2 = p.w*ia;
                float b0 = q.y*ib, b1 = q.z*ib, b2 = q.w*ib;
                float c0 = r.y*ic, c1 = r.z*ic, c2 = r.w*ic;
                float dab = a0*b0 + a1*b1 + a2*b2;
                float dac = a0*c0 + a1*c1 + a2*c2;
                float dbc = b0*c0 + b1*c1 + b2*c2;
                acc += 2.0f * (dab*dab + dac*dac + dbc*dbc);
            }
        }
    }

    // ---- Block reduction ----
    #pragma unroll
    for (int off = 16; off > 0; off >>= 1)
        acc += __shfl_xor_sync(0xFFFFFFFFu, acc, off);

    __shared__ float ws[WARPS];
    if (lane == 0) ws[w] = acc;
    __syncthreads();

    if (w == 0) {
        acc = (lane < WARPS) ? ws[lane] : 0.0f;
        #pragma unroll
        for (int off = 4; off > 0; off >>= 1)
            acc += __shfl_xor_sync(0xFFFFFFFFu, acc, off);
        if (lane == 0)
            atomicAdd(&g_accum, (double)acc);  // REDG, no-return
    }
}

__global__ void finalize_kernel(float* out, int nrows) {
    out[0] = (float)(g_accum / (double)nrows);
    g_accum = 0.0;  // reset for next launch / graph replay
}

extern "C" void kernel_launch(void* const* d_in, const int* in_sizes, int n_in,
                              void* d_out, int out_size) {
    const float4* in = (const float4*)d_in[0];
    float* out = (float*)d_out;
    int nrows = in_sizes[0] / 24;  // 24 floats per row
    int blocks = (nrows + TPB - 1) / TPB;

    loss_kernel<<<blocks, TPB>>>(in, nrows);
    finalize_kernel<<<1, 1>>>(out, nrows);
}